// round 12
// baseline (speedup 1.0000x reference)
#include <cuda_runtime.h>
#include <math.h>

#define K_COEF 20             // polynomial degree 19 in t = tanh(x/2)
#define MNODE  64             // Chebyshev projection nodes
#define KS2 4
#define NBASIS 8
#define NHID 16

// ---------- packed f32x2 helpers (sm_100+) ----------
__device__ __forceinline__ unsigned long long pack2(float lo, float hi) {
    unsigned long long r;
    asm("mov.b64 %0, {%1, %2};" : "=l"(r) : "f"(lo), "f"(hi));
    return r;
}
__device__ __forceinline__ void unpack2(unsigned long long v, float& lo, float& hi) {
    asm("mov.b64 {%0, %1}, %2;" : "=f"(lo), "=f"(hi) : "l"(v));
}
__device__ __forceinline__ unsigned long long fma2(unsigned long long a,
                                                   unsigned long long b,
                                                   unsigned long long c) {
    unsigned long long r;
    asm("fma.rn.f32x2 %0, %1, %2, %3;" : "=l"(r) : "l"(a), "l"(b), "l"(c));
    return r;
}

__device__ __forceinline__ float fast_tanh(float h) {
    return 1.0f - __fdividef(2.0f, __expf(2.0f * h) + 1.0f);
}

// F(a): RBF features + MLP, fast-math (only used to build the polynomial; ~1e-6 accuracy ample)
__device__ __forceinline__ float eval_F(float a,
                                        const float* __restrict__ basis,
                                        const float* __restrict__ w1,
                                        const float* __restrict__ b1,
                                        const float* __restrict__ w2,
                                        const float* __restrict__ b2) {
    float feats[NBASIS];
#pragma unroll
    for (int b = 0; b < NBASIS; ++b) {
        float s = 0.0f;
#pragma unroll
        for (int j = 0; j < KS2; ++j) {
            float df = a - basis[b * KS2 + j];
            s = fmaf(df, df, s);
        }
        feats[b] = __expf(-s);   // GAMMA = 1
    }
    float out = b2[0];
#pragma unroll
    for (int j = 0; j < NHID; ++j) {
        float h = b1[j];
#pragma unroll
        for (int b = 0; b < NBASIS; ++b)
            h = fmaf(feats[b], w1[b * NHID + j], h);
        out = fmaf(fast_tanh(h), w2[j], out);
    }
    return out;
}

__global__ void __launch_bounds__(256)
hybridconv_fused_kernel(const float4* __restrict__ data,
                        const float* __restrict__ conv_w,
                        const float* __restrict__ conv_b,
                        const float* __restrict__ basis,
                        const float* __restrict__ w1,
                        const float* __restrict__ b1,
                        const float* __restrict__ w2,
                        const float* __restrict__ b2,
                        float4* __restrict__ out4, int n4) {
    __shared__ float fnode[MNODE];
    __shared__ float cosm[MNODE][K_COEF];      // cos(k * theta_j)
    __shared__ float csh[K_COEF];              // Chebyshev coefficients
    __shared__ double Tm2[K_COEF], Tm1[K_COEF], Tc[K_COEF], mono[K_COEF];
    __shared__ unsigned long long cpk[K_COEF]; // packed {c,c} monomial coefficients

    const int tid = threadIdx.x;

    const float cw0 = __ldg(conv_w + 0);
    const float cw1 = __ldg(conv_w + 1);
    const float cw2 = __ldg(conv_w + 2);
    const float cw3 = __ldg(conv_w + 3);
    const float cb  = __ldg(conv_b);

    // ---- prologue: build the degree-19 polynomial (every block, redundantly) ----
    if (tid < MNODE) {
        float theta = (float)M_PI * ((float)tid + 0.5f) / (float)MNODE;
        float ct = __cosf(theta);                 // node t_j = cos(theta_j)
        float a  = 0.5f * (ct + 1.0f);            // activation in [0,1]
        fnode[tid] = eval_F(a, basis, w1, b1, w2, b2);
        // cos(k*theta) by recurrence: deterministic, no libm cosf
        float cm2 = 1.0f, cm1 = ct;
        cosm[tid][0] = 1.0f;
        cosm[tid][1] = cm1;
#pragma unroll
        for (int k = 2; k < K_COEF; ++k) {
            float c = fmaf(2.0f * ct, cm1, -cm2);
            cosm[tid][k] = c;
            cm2 = cm1; cm1 = c;
        }
    }
    __syncthreads();

    // Chebyshev coefficients: c_k = (2-delta_k0)/M * sum_j f_j cos(k theta_j)
    // Fixed summation order -> deterministic.
    if (tid < K_COEF) {
        float s = 0.0f;
#pragma unroll 8
        for (int j = 0; j < MNODE; ++j)
            s = fmaf(fnode[j], cosm[j][tid], s);
        csh[tid] = s * ((tid == 0) ? 1.0f : 2.0f) / (float)MNODE;
    }
    __syncthreads();

    // Chebyshev -> monomial in double: T0=[1], T1=[0,1], Tk = 2x*Tk-1 - Tk-2.
    if (tid < K_COEF) {
        Tm2[tid]  = (tid == 0) ? 1.0 : 0.0;
        Tm1[tid]  = (tid == 1) ? 1.0 : 0.0;
        mono[tid] = (double)csh[0] * Tm2[tid] + (double)csh[1] * Tm1[tid];
    }
    __syncthreads();
    for (int k = 2; k < K_COEF; ++k) {
        if (tid < K_COEF)
            Tc[tid] = ((tid > 0) ? 2.0 * Tm1[tid - 1] : 0.0) - Tm2[tid];
        __syncthreads();
        if (tid < K_COEF) {
            mono[tid] += (double)csh[k] * Tc[tid];
            Tm2[tid] = Tm1[tid];
            Tm1[tid] = Tc[tid];
        }
        __syncthreads();
    }
    if (tid < K_COEF) {
        float c = (float)mono[tid];
        cpk[tid] = pack2(c, c);
    }
    __syncthreads();

    // ---- main loop: dot -> t = tanh(x/2) -> packed-f32x2 Horner ----
    const int stride = gridDim.x * blockDim.x;
    for (int i = blockIdx.x * blockDim.x + tid; i < n4; i += stride) {
        const float4* p = data + 4 * i;
        float4 d0 = __ldcs(p + 0);
        float4 d1 = __ldcs(p + 1);
        float4 d2 = __ldcs(p + 2);
        float4 d3 = __ldcs(p + 3);
        float x0 = fmaf(d0.x, cw0, fmaf(d0.y, cw1, fmaf(d0.z, cw2, fmaf(d0.w, cw3, cb))));
        float x1 = fmaf(d1.x, cw0, fmaf(d1.y, cw1, fmaf(d1.z, cw2, fmaf(d1.w, cw3, cb))));
        float x2 = fmaf(d2.x, cw0, fmaf(d2.y, cw1, fmaf(d2.z, cw2, fmaf(d2.w, cw3, cb))));
        float x3 = fmaf(d3.x, cw0, fmaf(d3.y, cw1, fmaf(d3.z, cw2, fmaf(d3.w, cw3, cb))));
        // t = tanh(x/2) = 1 - 2/(e^x + 1); saturates exactly for extreme logits
        float t0 = 1.0f - __fdividef(2.0f, __expf(x0) + 1.0f);
        float t1 = 1.0f - __fdividef(2.0f, __expf(x1) + 1.0f);
        float t2 = 1.0f - __fdividef(2.0f, __expf(x2) + 1.0f);
        float t3 = 1.0f - __fdividef(2.0f, __expf(x3) + 1.0f);

        unsigned long long u01 = pack2(t0, t1);
        unsigned long long u23 = pack2(t2, t3);
        unsigned long long p01 = cpk[K_COEF - 1];
        unsigned long long p23 = p01;
#pragma unroll
        for (int k = K_COEF - 2; k >= 0; --k) {
            unsigned long long c = cpk[k];   // LDS.64 same-address broadcast
            p01 = fma2(p01, u01, c);
            p23 = fma2(p23, u23, c);
        }
        float4 r;
        unpack2(p01, r.x, r.y);
        unpack2(p23, r.z, r.w);
        __stcs(&out4[i], r);
    }
}

extern "C" void kernel_launch(void* const* d_in, const int* in_sizes, int n_in,
                              void* d_out, int out_size) {
    // metadata order: data, conv_w, conv_b, basis, w1, b1, w2, b2
    const float4* data   = (const float4*)d_in[0];
    const float*  conv_w = (const float*)d_in[1];
    const float*  conv_b = (const float*)d_in[2];
    const float*  basis  = (const float*)d_in[3];
    const float*  w1     = (const float*)d_in[4];
    const float*  b1     = (const float*)d_in[5];
    const float*  w2     = (const float*)d_in[6];
    const float*  b2     = (const float*)d_in[7];
    float4* out4 = (float4*)d_out;

    const int n  = in_sizes[0] / 4;   // N patches
    const int n4 = n / 4;             // float4 output groups

    hybridconv_fused_kernel<<<148 * 8, 256>>>(data, conv_w, conv_b,
                                              basis, w1, b1, w2, b2,
                                              out4, n4);
}

// round 14
// speedup vs baseline: 1.2526x; 1.2526x over previous
#include <cuda_runtime.h>
#include <math.h>

#define K_COEF 20             // polynomial degree 19 in t = tanh(x/2)
#define MNODE  64             // Chebyshev projection nodes
#define KS2 4
#define NBASIS 8
#define NHID 16

__device__ float g_coef[K_COEF];   // monomial coefficients c[0] + c[1] t + ...

// ---------- packed f32x2 helpers (sm_100+) ----------
__device__ __forceinline__ unsigned long long pack2(float lo, float hi) {
    unsigned long long r;
    asm("mov.b64 %0, {%1, %2};" : "=l"(r) : "f"(lo), "f"(hi));
    return r;
}
__device__ __forceinline__ void unpack2(unsigned long long v, float& lo, float& hi) {
    asm("mov.b64 {%0, %1}, %2;" : "=f"(lo), "=f"(hi) : "l"(v));
}
__device__ __forceinline__ unsigned long long fma2(unsigned long long a,
                                                   unsigned long long b,
                                                   unsigned long long c) {
    unsigned long long r;
    asm("fma.rn.f32x2 %0, %1, %2, %3;" : "=l"(r) : "l"(a), "l"(b), "l"(c));
    return r;
}

__device__ __forceinline__ float fast_tanh(float h) {
    return 1.0f - __fdividef(2.0f, __expf(2.0f * h) + 1.0f);
}

// F(a): RBF features + MLP (fast-math; feeds the polynomial fit only)
__device__ __forceinline__ float eval_F(float a,
                                        const float* __restrict__ basis,
                                        const float* __restrict__ w1,
                                        const float* __restrict__ b1,
                                        const float* __restrict__ w2,
                                        const float* __restrict__ b2) {
    float feats[NBASIS];
#pragma unroll
    for (int b = 0; b < NBASIS; ++b) {
        float s = 0.0f;
#pragma unroll
        for (int j = 0; j < KS2; ++j) {
            float df = a - basis[b * KS2 + j];
            s = fmaf(df, df, s);
        }
        feats[b] = __expf(-s);   // GAMMA = 1
    }
    float out = b2[0];
#pragma unroll
    for (int j = 0; j < NHID; ++j) {
        float h = b1[j];
#pragma unroll
        for (int b = 0; b < NBASIS; ++b)
            h = fmaf(feats[b], w1[b * NHID + j], h);
        out = fmaf(fast_tanh(h), w2[j], out);
    }
    return out;
}

// ---------- build: one block, 64 threads, no libm cosf ----------
__global__ void __launch_bounds__(MNODE)
build_poly_kernel(const float* __restrict__ basis,
                  const float* __restrict__ w1,
                  const float* __restrict__ b1,
                  const float* __restrict__ w2,
                  const float* __restrict__ b2) {
    __shared__ float fnode[MNODE];
    __shared__ float cosm[MNODE][K_COEF];      // cos(k * theta_j)
    __shared__ float csh[K_COEF];
    __shared__ double Tm2[K_COEF], Tm1[K_COEF], Tc[K_COEF], mono[K_COEF];

    const int tid = threadIdx.x;

    // node tid: theta = pi*(tid+0.5)/M, t = cos(theta), a = (t+1)/2
    {
        float theta = (float)M_PI * ((float)tid + 0.5f) / (float)MNODE;
        float ct = __cosf(theta);
        float a  = 0.5f * (ct + 1.0f);
        fnode[tid] = eval_F(a, basis, w1, b1, w2, b2);
        // cos(k*theta) by Chebyshev recurrence — one __cosf total
        float cm2 = 1.0f, cm1 = ct;
        cosm[tid][0] = 1.0f;
        cosm[tid][1] = cm1;
#pragma unroll
        for (int k = 2; k < K_COEF; ++k) {
            float c = fmaf(2.0f * ct, cm1, -cm2);
            cosm[tid][k] = c;
            cm2 = cm1; cm1 = c;
        }
    }
    __syncthreads();

    // Chebyshev coefficients c_k (fixed-order 64-term sum, deterministic)
    if (tid < K_COEF) {
        float s = 0.0f;
#pragma unroll 8
        for (int j = 0; j < MNODE; ++j)
            s = fmaf(fnode[j], cosm[j][tid], s);
        csh[tid] = s * ((tid == 0) ? 1.0f : 2.0f) / (float)MNODE;
    }
    __syncthreads();

    // Chebyshev -> monomial in double: T0=[1], T1=[0,1], Tk = 2x*Tk-1 - Tk-2.
    if (tid < K_COEF) {
        Tm2[tid]  = (tid == 0) ? 1.0 : 0.0;
        Tm1[tid]  = (tid == 1) ? 1.0 : 0.0;
        mono[tid] = (double)csh[0] * Tm2[tid] + (double)csh[1] * Tm1[tid];
    }
    __syncthreads();
    for (int k = 2; k < K_COEF; ++k) {
        if (tid < K_COEF)
            Tc[tid] = ((tid > 0) ? 2.0 * Tm1[tid - 1] : 0.0) - Tm2[tid];
        __syncthreads();
        if (tid < K_COEF) {
            mono[tid] += (double)csh[k] * Tc[tid];
            Tm2[tid] = Tm1[tid];
            Tm1[tid] = Tc[tid];
        }
        __syncthreads();
    }
    if (tid < K_COEF) g_coef[tid] = (float)mono[tid];
}

// ---------- main: dot -> t=tanh(x/2) -> packed-f32x2 Horner (R11 loop, unchanged) ----------
__global__ void __launch_bounds__(256)
hybridconv_main_kernel(const float4* __restrict__ data,
                       const float* __restrict__ conv_w,
                       const float* __restrict__ conv_b,
                       float4* __restrict__ out4, int n4) {
    __shared__ unsigned long long cpk[K_COEF];   // packed {c,c}

    const float cw0 = __ldg(conv_w + 0);
    const float cw1 = __ldg(conv_w + 1);
    const float cw2 = __ldg(conv_w + 2);
    const float cw3 = __ldg(conv_w + 3);
    const float cb  = __ldg(conv_b);

#if __CUDA_ARCH__ >= 900
    cudaGridDependencySynchronize();   // PDL: wait for build kernel
#endif
    if (threadIdx.x < K_COEF) {
        float c = g_coef[threadIdx.x];
        cpk[threadIdx.x] = pack2(c, c);
    }
    __syncthreads();

    const int stride = gridDim.x * blockDim.x;
    for (int i = blockIdx.x * blockDim.x + threadIdx.x; i < n4; i += stride) {
        const float4* p = data + 4 * i;
        float4 d0 = __ldcs(p + 0);
        float4 d1 = __ldcs(p + 1);
        float4 d2 = __ldcs(p + 2);
        float4 d3 = __ldcs(p + 3);
        float x0 = fmaf(d0.x, cw0, fmaf(d0.y, cw1, fmaf(d0.z, cw2, fmaf(d0.w, cw3, cb))));
        float x1 = fmaf(d1.x, cw0, fmaf(d1.y, cw1, fmaf(d1.z, cw2, fmaf(d1.w, cw3, cb))));
        float x2 = fmaf(d2.x, cw0, fmaf(d2.y, cw1, fmaf(d2.z, cw2, fmaf(d2.w, cw3, cb))));
        float x3 = fmaf(d3.x, cw0, fmaf(d3.y, cw1, fmaf(d3.z, cw2, fmaf(d3.w, cw3, cb))));
        // t = tanh(x/2) = 1 - 2/(e^x + 1); saturates exactly for extreme logits
        float t0 = 1.0f - __fdividef(2.0f, __expf(x0) + 1.0f);
        float t1 = 1.0f - __fdividef(2.0f, __expf(x1) + 1.0f);
        float t2 = 1.0f - __fdividef(2.0f, __expf(x2) + 1.0f);
        float t3 = 1.0f - __fdividef(2.0f, __expf(x3) + 1.0f);

        unsigned long long u01 = pack2(t0, t1);
        unsigned long long u23 = pack2(t2, t3);
        unsigned long long p01 = cpk[K_COEF - 1];
        unsigned long long p23 = p01;
#pragma unroll
        for (int k = K_COEF - 2; k >= 0; --k) {
            unsigned long long c = cpk[k];   // LDS.64 same-address broadcast
            p01 = fma2(p01, u01, c);
            p23 = fma2(p23, u23, c);
        }
        float4 r;
        unpack2(p01, r.x, r.y);
        unpack2(p23, r.z, r.w);
        __stcs(&out4[i], r);
    }
}

extern "C" void kernel_launch(void* const* d_in, const int* in_sizes, int n_in,
                              void* d_out, int out_size) {
    // metadata order: data, conv_w, conv_b, basis, w1, b1, w2, b2
    const float4* data   = (const float4*)d_in[0];
    const float*  conv_w = (const float*)d_in[1];
    const float*  conv_b = (const float*)d_in[2];
    const float*  basis  = (const float*)d_in[3];
    const float*  w1     = (const float*)d_in[4];
    const float*  b1     = (const float*)d_in[5];
    const float*  w2     = (const float*)d_in[6];
    const float*  b2     = (const float*)d_in[7];
    float4* out4 = (float4*)d_out;

    const int n  = in_sizes[0] / 4;   // N patches
    const int n4 = n / 4;             // float4 output groups

    build_poly_kernel<<<1, MNODE>>>(basis, w1, b1, w2, b2);

    cudaLaunchConfig_t cfg = {};
    cfg.gridDim  = dim3(148 * 8, 1, 1);
    cfg.blockDim = dim3(256, 1, 1);
    cfg.dynamicSmemBytes = 0;
    cudaLaunchAttribute attr[1];
    attr[0].id = cudaLaunchAttributeProgrammaticStreamSerialization;
    attr[0].val.programmaticStreamSerializationAllowed = 1;
    cfg.attrs = attr;
    cfg.numAttrs = 1;
    cudaLaunchKernelEx(&cfg, hybridconv_main_kernel, data, conv_w, conv_b, out4, n4);
}

// round 15
// speedup vs baseline: 1.3276x; 1.0599x over previous
#include <cuda_runtime.h>
#include <math.h>

#define K_COEF 20             // polynomial degree 19 in t = tanh(x/2)
#define MNODE  64             // Chebyshev projection nodes
#define KS2 4
#define NBASIS 8
#define NHID 16

// ---------- compile-time Chebyshev -> monomial matrix ----------
// TMAT.m[k][j] = coefficient of t^j in T_k(t).  Exact integers (< 2^19) in double.
struct TMat { double m[K_COEF][K_COEF]; };
constexpr TMat make_tmat() {
    TMat t{};
    t.m[0][0] = 1.0;
    t.m[1][1] = 1.0;
    for (int k = 2; k < K_COEF; ++k) {
        for (int j = 0; j < K_COEF; ++j) {
            double v = -t.m[k - 2][j];
            if (j > 0) v += 2.0 * t.m[k - 1][j - 1];
            t.m[k][j] = v;
        }
    }
    return t;
}
__constant__ TMat TMAT = make_tmat();

// ---------- packed f32x2 helpers (sm_100+) ----------
__device__ __forceinline__ unsigned long long pack2(float lo, float hi) {
    unsigned long long r;
    asm("mov.b64 %0, {%1, %2};" : "=l"(r) : "f"(lo), "f"(hi));
    return r;
}
__device__ __forceinline__ void unpack2(unsigned long long v, float& lo, float& hi) {
    asm("mov.b64 {%0, %1}, %2;" : "=f"(lo), "=f"(hi) : "l"(v));
}
__device__ __forceinline__ unsigned long long fma2(unsigned long long a,
                                                   unsigned long long b,
                                                   unsigned long long c) {
    unsigned long long r;
    asm("fma.rn.f32x2 %0, %1, %2, %3;" : "=l"(r) : "l"(a), "l"(b), "l"(c));
    return r;
}

__device__ __forceinline__ float fast_tanh(float h) {
    return 1.0f - __fdividef(2.0f, __expf(2.0f * h) + 1.0f);
}

// F(a): RBF features + MLP (fast-math; feeds the polynomial fit only)
__device__ __forceinline__ float eval_F(float a,
                                        const float* __restrict__ basis,
                                        const float* __restrict__ w1,
                                        const float* __restrict__ b1,
                                        const float* __restrict__ w2,
                                        const float* __restrict__ b2) {
    float feats[NBASIS];
#pragma unroll
    for (int b = 0; b < NBASIS; ++b) {
        float s = 0.0f;
#pragma unroll
        for (int j = 0; j < KS2; ++j) {
            float df = a - basis[b * KS2 + j];
            s = fmaf(df, df, s);
        }
        feats[b] = __expf(-s);   // GAMMA = 1
    }
    float out = b2[0];
#pragma unroll
    for (int j = 0; j < NHID; ++j) {
        float h = b1[j];
#pragma unroll
        for (int b = 0; b < NBASIS; ++b)
            h = fmaf(feats[b], w1[b * NHID + j], h);
        out = fmaf(fast_tanh(h), w2[j], out);
    }
    return out;
}

__global__ void __launch_bounds__(256)
hybridconv_fused_kernel(const float4* __restrict__ data,
                        const float* __restrict__ conv_w,
                        const float* __restrict__ conv_b,
                        const float* __restrict__ basis,
                        const float* __restrict__ w1,
                        const float* __restrict__ b1,
                        const float* __restrict__ w2,
                        const float* __restrict__ b2,
                        float4* __restrict__ out4, int n4) {
    __shared__ float fnode[MNODE];
    __shared__ float cosm[MNODE][K_COEF];        // cos(k * theta_j)
    __shared__ float csh[K_COEF];                // Chebyshev coefficients
    __shared__ unsigned long long cpk[K_COEF];   // packed {c,c} monomial coefficients

    const int tid = threadIdx.x;

    const float cw0 = __ldg(conv_w + 0);
    const float cw1 = __ldg(conv_w + 1);
    const float cw2 = __ldg(conv_w + 2);
    const float cw3 = __ldg(conv_w + 3);
    const float cb  = __ldg(conv_b);

    // ---- cheap prologue (3 barriers, ~2k cycles, once per resident block) ----
    if (tid < MNODE) {
        float theta = (float)M_PI * ((float)tid + 0.5f) / (float)MNODE;
        float ct = __cosf(theta);                 // node t_j = cos(theta_j)
        float a  = 0.5f * (ct + 1.0f);            // activation in [0,1]
        fnode[tid] = eval_F(a, basis, w1, b1, w2, b2);
        float cm2 = 1.0f, cm1 = ct;               // cos(k*theta) recurrence
        cosm[tid][0] = 1.0f;
        cosm[tid][1] = cm1;
#pragma unroll
        for (int k = 2; k < K_COEF; ++k) {
            float c = fmaf(2.0f * ct, cm1, -cm2);
            cosm[tid][k] = c;
            cm2 = cm1; cm1 = c;
        }
    }
    __syncthreads();

    if (tid < K_COEF) {
        float s = 0.0f;
#pragma unroll 8
        for (int j = 0; j < MNODE; ++j)
            s = fmaf(fnode[j], cosm[j][tid], s);   // fixed order: deterministic
        csh[tid] = s * ((tid == 0) ? 1.0f : 2.0f) / (float)MNODE;
    }
    __syncthreads();

    if (tid < K_COEF) {
        // monomial coeff j = sum_k csh[k] * TMAT[k][j]  (double, exact matrix)
        double m = 0.0;
#pragma unroll
        for (int k = 0; k < K_COEF; ++k)
            m += (double)csh[k] * TMAT.m[k][tid];
        float c = (float)m;
        cpk[tid] = pack2(c, c);
    }
    __syncthreads();

    // ---- main loop: dot -> t = tanh(x/2) -> packed-f32x2 Horner ----
    const int stride = gridDim.x * blockDim.x;
    for (int i = blockIdx.x * blockDim.x + tid; i < n4; i += stride) {
        const float4* p = data + 4 * i;
        float4 d0 = __ldcs(p + 0);
        float4 d1 = __ldcs(p + 1);
        float4 d2 = __ldcs(p + 2);
        float4 d3 = __ldcs(p + 3);
        float x0 = fmaf(d0.x, cw0, fmaf(d0.y, cw1, fmaf(d0.z, cw2, fmaf(d0.w, cw3, cb))));
        float x1 = fmaf(d1.x, cw0, fmaf(d1.y, cw1, fmaf(d1.z, cw2, fmaf(d1.w, cw3, cb))));
        float x2 = fmaf(d2.x, cw0, fmaf(d2.y, cw1, fmaf(d2.z, cw2, fmaf(d2.w, cw3, cb))));
        float x3 = fmaf(d3.x, cw0, fmaf(d3.y, cw1, fmaf(d3.z, cw2, fmaf(d3.w, cw3, cb))));
        // t = tanh(x/2) = 1 - 2/(e^x + 1); saturates exactly for extreme logits
        float t0 = 1.0f - __fdividef(2.0f, __expf(x0) + 1.0f);
        float t1 = 1.0f - __fdividef(2.0f, __expf(x1) + 1.0f);
        float t2 = 1.0f - __fdividef(2.0f, __expf(x2) + 1.0f);
        float t3 = 1.0f - __fdividef(2.0f, __expf(x3) + 1.0f);

        unsigned long long u01 = pack2(t0, t1);
        unsigned long long u23 = pack2(t2, t3);
        unsigned long long p01 = cpk[K_COEF - 1];
        unsigned long long p23 = p01;
#pragma unroll
        for (int k = K_COEF - 2; k >= 0; --k) {
            unsigned long long c = cpk[k];   // LDS.64 same-address broadcast
            p01 = fma2(p01, u01, c);
            p23 = fma2(p23, u23, c);
        }
        float4 r;
        unpack2(p01, r.x, r.y);
        unpack2(p23, r.z, r.w);
        __stcs(&out4[i], r);
    }
}

extern "C" void kernel_launch(void* const* d_in, const int* in_sizes, int n_in,
                              void* d_out, int out_size) {
    // metadata order: data, conv_w, conv_b, basis, w1, b1, w2, b2
    const float4* data   = (const float4*)d_in[0];
    const float*  conv_w = (const float*)d_in[1];
    const float*  conv_b = (const float*)d_in[2];
    const float*  basis  = (const float*)d_in[3];
    const float*  w1     = (const float*)d_in[4];
    const float*  b1     = (const float*)d_in[5];
    const float*  w2     = (const float*)d_in[6];
    const float*  b2     = (const float*)d_in[7];
    float4* out4 = (float4*)d_out;

    const int n  = in_sizes[0] / 4;   // N patches
    const int n4 = n / 4;             // float4 output groups

    // One wave: 3 blocks/SM at ~77 regs; prologue paid exactly once per slot.
    hybridconv_fused_kernel<<<148 * 3, 256>>>(data, conv_w, conv_b,
                                              basis, w1, b1, w2, b2,
                                              out4, n4);
}